// round 14
// baseline (speedup 1.0000x reference)
#include <cuda_runtime.h>
#include <cuda_fp16.h>

// ---------- packed f16x2 helpers ----------
__device__ __forceinline__ unsigned pkhf(float lo, float hi) {
    unsigned d; asm("cvt.rn.f16x2.f32 %0, %1, %2;" : "=r"(d) : "f"(hi), "f"(lo)); return d;
}
__device__ __forceinline__ unsigned hmin2(unsigned a, unsigned b) {
    unsigned d; asm("min.f16x2 %0, %1, %2;" : "=r"(d) : "r"(a), "r"(b)); return d;
}
__device__ __forceinline__ unsigned hmax2(unsigned a, unsigned b) {
    unsigned d; asm("max.f16x2 %0, %1, %2;" : "=r"(d) : "r"(a), "r"(b)); return d;
}
__device__ __forceinline__ unsigned hadd2(unsigned a, unsigned b) {
    unsigned d; asm("add.rn.f16x2 %0, %1, %2;" : "=r"(d) : "r"(a), "r"(b)); return d;
}
__device__ __forceinline__ unsigned hex2(unsigned a) {
    unsigned d; asm("ex2.approx.f16x2 %0, %1;" : "=r"(d) : "r"(a)); return d;
}
__device__ __forceinline__ unsigned hfma2(unsigned a, unsigned b, unsigned c) {
    unsigned d; asm("fma.rn.f16x2 %0, %1, %2, %3;" : "=r"(d) : "r"(a), "r"(b), "r"(c)); return d;
}
// x = h*log2e (f16x2). Returns elu(h)+1 = max(x,0)*ln2 + exp2(min(x,0)).
__device__ __forceinline__ unsigned elu2h(unsigned x, unsigned ln2) {
    return hfma2(hmax2(x, 0u), ln2, hex2(hmin2(x, 0u)));
}
// layer-1 MMA: f16 inputs, f16 accumulators (D packed f16x2, 2 regs)
__device__ __forceinline__ void mma_h(unsigned& d0, unsigned& d1,
                                      unsigned a0, unsigned a1, unsigned a2, unsigned a3,
                                      unsigned b0, unsigned b1) {
    asm("mma.sync.aligned.m16n8k16.row.col.f16.f16.f16.f16 "
        "{%0,%1},{%2,%3,%4,%5},{%6,%7},{%0,%1};"
        : "+r"(d0), "+r"(d1)
        : "r"(a0), "r"(a1), "r"(a2), "r"(a3), "r"(b0), "r"(b1));
}
// layer-2 MMA: f16 inputs, f32 accumulators
__device__ __forceinline__ void mma_f(float& d0, float& d1, float& d2, float& d3,
                                      unsigned a0, unsigned a1, unsigned a2, unsigned a3,
                                      unsigned b0, unsigned b1) {
    asm("mma.sync.aligned.m16n8k16.row.col.f32.f16.f16.f32 "
        "{%0,%1,%2,%3},{%4,%5,%6,%7},{%8,%9},{%0,%1,%2,%3};"
        : "+f"(d0), "+f"(d1), "+f"(d2), "+f"(d3)
        : "r"(a0), "r"(a1), "r"(a2), "r"(a3), "r"(b0), "r"(b1));
}

// ---------- precomputed packed buffers (one entry per weight-block) ----------
__device__ uint4    g_w1c[256][192];   // [q][kb][g]: 4 f16x2 k-pairs of w1*log2e
__device__ uint4    g_w2c[256][192];   // [(4kb+q)][g]: f16x2 h-pairs, n=g / n=g+8
__device__ uint2    g_bbp[256][24];    // [4kb+q]: f16x2 bias pairs (sub0, sub1), *log2e
__device__ float4   g_eps[256][8];     // [j]: {b2e[2j], b2e[2j+1], sc[2j], sc[2j+1]}
__device__ unsigned g_ehp[256][256];   // [t][q]: f16x2 {eh[t][2q],eh[t][2q+1]}*log2e
__device__ unsigned g_ewp[256][256];   // [t][q]: f16x2 {ew[t][2q],ew[t][2q+1]}*log2e

// Pack kernel: stage w1/w2 into smem with fully-coalesced float4 LDGs, then
// pack fragments from smem (cheap LDS) and store coalesced uint4.
__global__ __launch_bounds__(256) void pack_kernel(
    const float* __restrict__ w1, const float* __restrict__ b1,
    const float* __restrict__ emb_h, const float* __restrict__ emb_w,
    const float* __restrict__ w2, const float* __restrict__ b2,
    const float* __restrict__ scales)
{
    __shared__ __align__(16) float sw1[1536];   // [16][96]
    __shared__ __align__(16) float sw2[1536];   // [96][16]
    __shared__ float s_psum[8 * 16];
    const int b   = blockIdx.x;
    const int tid = threadIdx.x;
    const float L2E = 1.44269504f;

    // coalesced stage: 384 float4 each, 256 threads
    {
        const float4* p1 = reinterpret_cast<const float4*>(w1 + b * 1536);
        const float4* p2 = reinterpret_cast<const float4*>(w2 + b * 1536);
        float4* d1 = reinterpret_cast<float4*>(sw1);
        float4* d2 = reinterpret_cast<float4*>(sw2);
        d1[tid] = p1[tid];
        d2[tid] = p2[tid];
        if (tid < 128) {
            d1[256 + tid] = p1[256 + tid];
            d2[256 + tid] = p2[256 + tid];
        }
    }
    __syncthreads();

    // parallel b2_eff colsum partials: 128 threads, 12 f16-rounded adds each
    if (tid < 128) {
        const int o = tid & 15, p = tid >> 4;
        float s = 0.f;
        #pragma unroll
        for (int h = 0; h < 12; ++h)
            s += __half2float(__float2half(sw2[(12 * p + h) * 16 + o]));
        s_psum[p * 16 + o] = s;
    }

    if (tid < 192) {
        // w1 fragment pack (scaled by log2e): idx = q*48 + kb*8 + g
        const int qq = tid / 48, r = tid - qq * 48;
        const int kb = r >> 3, gg = r & 7;
        const int h0 = 16 * kb + gg;
        g_w1c[b][tid] = make_uint4(
            pkhf(L2E * sw1[(2*qq)*96 + h0],       L2E * sw1[(2*qq+1)*96 + h0]),
            pkhf(L2E * sw1[(2*qq+8)*96 + h0],     L2E * sw1[(2*qq+9)*96 + h0]),
            pkhf(L2E * sw1[(2*qq)*96 + h0 + 8],   L2E * sw1[(2*qq+1)*96 + h0 + 8]),
            pkhf(L2E * sw1[(2*qq+8)*96 + h0 + 8], L2E * sw1[(2*qq+9)*96 + h0 + 8]));
        // w2 fragment pack: idx = (4kb+q)*8 + g
        const int kq = tid >> 3, g2 = tid & 7;
        const int hh = (kq >> 2) * 16 + 2 * (kq & 3);
        g_w2c[b][tid] = make_uint4(
            pkhf(sw2[hh*16 + g2],         sw2[(hh+1)*16 + g2]),
            pkhf(sw2[(hh+8)*16 + g2],     sw2[(hh+9)*16 + g2]),
            pkhf(sw2[hh*16 + 8 + g2],     sw2[(hh+1)*16 + 8 + g2]),
            pkhf(sw2[(hh+8)*16 + 8 + g2], sw2[(hh+9)*16 + 8 + g2]));
    }
    if (tid < 24) {   // bias packs (scaled): kq = 4kb+q -> pairs at 16kb+2q, 16kb+8+2q
        const int h0 = (tid >> 2) * 16 + 2 * (tid & 3);
        const float* pb1 = b1 + b * 96;
        g_bbp[b][tid] = make_uint2(
            pkhf(L2E * pb1[h0],     L2E * pb1[h0 + 1]),
            pkhf(L2E * pb1[h0 + 8], L2E * pb1[h0 + 9]));
    }
    {   // positional-emb pairs (scaled): coalesced float2 loads
        const float2 eh = reinterpret_cast<const float2*>(emb_h + b * 512)[tid];
        const float2 ew = reinterpret_cast<const float2*>(emb_w + b * 512)[tid];
        g_ehp[b][tid] = pkhf(L2E * eh.x, L2E * eh.y);
        g_ewp[b][tid] = pkhf(L2E * ew.x, L2E * ew.y);
    }
    __syncthreads();
    if (tid < 16) {   // b2_eff = b2 - colsum(f16(w2)): exact cancellation of +1 shift
        float s = b2[b * 16 + tid];
        #pragma unroll
        for (int p = 0; p < 8; ++p) s -= s_psum[p * 16 + tid];
        float* ef = reinterpret_cast<float*>(g_eps[b]);
        ef[4 * (tid >> 1) + (tid & 1)]     = s;
        ef[4 * (tid >> 1) + 2 + (tid & 1)] = scales[b * 16 + tid];
    }
}

// Fixed shapes: A 4096x4096 fp32; 256 weight-blocks of 64x64=4096 4x4-tiles;
// RNG_HID=96, RNG_POS_EMB=8.
// Grid 4096 CTAs x 256 threads (8 warps); warp w fuses its two M-blocks
// (same tile row, twb0 and twb0+16) kb-by-kb through the hidden dim.
// A-fragment LDGs are issued FIRST (before smem staging) so their DRAM
// latency overlaps the staging reads + barrier.
#define W1Q_STRIDE 50   // uint4 q-stride: bank = (8q+4g)%32, conflict-free
#define W2R_STRIDE 10   // uint4 row-stride: bank = (8q+4g)%32, conflict-free

__global__ __launch_bounds__(256, 3) void adapter_mma_kernel(
    const float* __restrict__ A,        // [4096,4096]
    float* __restrict__ out)            // [4096,4096]
{
    __shared__ __align__(16) uint4    s_w1c[4 * W1Q_STRIDE];
    __shared__ __align__(16) uint4    s_w2c[24 * W2R_STRIDE];
    __shared__ __align__(16) uint2    s_bbp[24];
    __shared__ __align__(16) unsigned s_ehp[256];
    __shared__ __align__(16) unsigned s_ewp[256];
    __shared__ __align__(16) float4   s_eps[8];

    const int b     = blockIdx.x >> 4;
    const int chunk = blockIdx.x & 15;
    const int tid   = threadIdx.x;
    const int warp  = tid >> 5;
    const int lane  = tid & 31;
    const int g     = lane >> 2;     // 0..7
    const int q     = lane & 3;      // 0..3

    // ---- geometry (both M-blocks share tile row; twb1 = twb0 + 16) ----
    const int brow = (b >> 4) << 8;
    const int bcol = (b & 15) << 8;
    const int th   = chunk * 4 + (warp >> 1);
    const int twb0 = (warp & 1) << 5;           // 0 or 32
    const int rowA = brow + th * 4;
    const int rsel = q >> 1;

    // ---- A fragments FIRST: DRAM latency overlaps staging below ----
    const float* pr0 = A + (size_t)(rowA + rsel)     * 4096 + bcol + (twb0 + g) * 4 + 2 * (q & 1);
    const float* pr2 = A + (size_t)(rowA + 2 + rsel) * 4096 + bcol + (twb0 + g) * 4 + 2 * (q & 1);
    float2 v[2][4];
    v[0][0] = *reinterpret_cast<const float2*>(pr0);
    v[0][1] = *reinterpret_cast<const float2*>(pr0 + 32);
    v[0][2] = *reinterpret_cast<const float2*>(pr2);
    v[0][3] = *reinterpret_cast<const float2*>(pr2 + 32);
    v[1][0] = *reinterpret_cast<const float2*>(pr0 + 64);
    v[1][1] = *reinterpret_cast<const float2*>(pr0 + 96);
    v[1][2] = *reinterpret_cast<const float2*>(pr2 + 64);
    v[1][3] = *reinterpret_cast<const float2*>(pr2 + 96);

    // ---- staging: straight vectorized copies of prepacked data ----
    if (tid < 192) {
        const int qq = tid / 48, r = tid - qq * 48;
        s_w1c[qq * W1Q_STRIDE + r] = g_w1c[b][tid];
        const int kq = tid >> 3, gg = tid & 7;
        s_w2c[kq * W2R_STRIDE + gg] = g_w2c[b][tid];
    } else {
        const int j = tid - 192;   // 0..63
        reinterpret_cast<uint4*>(s_ehp)[j] = reinterpret_cast<const uint4*>(g_ehp[b])[j];
        reinterpret_cast<uint4*>(s_ewp)[j] = reinterpret_cast<const uint4*>(g_ewp[b])[j];
    }
    if (tid < 24)            s_bbp[tid] = g_bbp[b][tid];
    else if (tid < 32)       s_eps[tid - 24] = g_eps[b][tid - 24];

    unsigned Af[2][4];
    #pragma unroll
    for (int it = 0; it < 2; ++it)
        #pragma unroll
        for (int j = 0; j < 4; ++j) Af[it][j] = pkhf(v[it][j].x, v[it][j].y);

    __syncthreads();

    const unsigned PK_LN2 = pkhf(0.69314718f, 0.69314718f);

    float o[2][8];
    #pragma unroll
    for (int it = 0; it < 2; ++it)
        #pragma unroll
        for (int j = 0; j < 8; ++j) o[it][j] = 0.f;

    // ---- fused mainloop: 6 kb-steps over hidden dim ----
    #pragma unroll
    for (int kb = 0; kb < 6; ++kb) {
        const uint4 W1 = s_w1c[q * W1Q_STRIDE + kb * 8 + g];
        const uint2 BB = s_bbp[kb * 4 + q];
        unsigned ka[2][4];
        // sub 0 (hidden cols 16kb+2q, +1): C-init = bias (+ row emb at kb==0)
        {
            unsigned c0 = BB.x;
            if (kb == 0) c0 = hadd2(c0, s_ehp[th * 4 + q]);
            #pragma unroll
            for (int it = 0; it < 2; ++it) {
                unsigned d0 = c0, d1 = c0;
                mma_h(d0, d1, Af[it][0], Af[it][1], Af[it][2], Af[it][3], W1.x, W1.y);
                ka[it][0] = elu2h(d0, PK_LN2);
                ka[it][1] = elu2h(d1, PK_LN2);
            }
        }
        // sub 1 (hidden cols 16kb+8+2q, +1): C-init = bias (+ col emb at kb==0)
        {
            #pragma unroll
            for (int it = 0; it < 2; ++it) {
                unsigned d0 = BB.y, d1 = BB.y;
                if (kb == 0) {
                    const int twb = twb0 + 16 * it;
                    d0 = hadd2(d0, s_ewp[(twb + g) * 4 + q]);
                    d1 = hadd2(d1, s_ewp[(twb + g + 8) * 4 + q]);
                }
                mma_h(d0, d1, Af[it][0], Af[it][1], Af[it][2], Af[it][3], W1.z, W1.w);
                ka[it][2] = elu2h(d0, PK_LN2);
                ka[it][3] = elu2h(d1, PK_LN2);
            }
        }
        // layer-2 k-step: both n-blocks from one LDS.128
        const uint4 W2 = s_w2c[(4 * kb + q) * W2R_STRIDE + g];
        #pragma unroll
        for (int it = 0; it < 2; ++it) {
            mma_f(o[it][0], o[it][1], o[it][2], o[it][3],
                  ka[it][0], ka[it][1], ka[it][2], ka[it][3], W2.x, W2.y);
            mma_f(o[it][4], o[it][5], o[it][6], o[it][7],
                  ka[it][0], ka[it][1], ka[it][2], ka[it][3], W2.z, W2.w);
        }
    }

    // ---- epilogue: out = mlp + b2_eff + flat*scales (flat = register v) ----
    const float4 E0 = s_eps[q];       // ob = 2q
    const float4 E1 = s_eps[4 + q];   // ob = 8+2q
    #pragma unroll
    for (int it = 0; it < 2; ++it) {
        const int colO = bcol + (twb0 + 16 * it + g) * 4 + 2 * (q & 1);
        {   // nb2 = 0: row rowA+rsel, values v[it][0], v[it][1]
            const size_t rowOff = (size_t)(rowA + rsel) * 4096;
            float2 ra, rb;
            ra.x = o[it][0] + E0.x + v[it][0].x * E0.z;
            ra.y = o[it][1] + E0.y + v[it][0].y * E0.w;
            rb.x = o[it][2] + E0.x + v[it][1].x * E0.z;
            rb.y = o[it][3] + E0.y + v[it][1].y * E0.w;
            *reinterpret_cast<float2*>(out + rowOff + colO)      = ra;
            *reinterpret_cast<float2*>(out + rowOff + colO + 32) = rb;
        }
        {   // nb2 = 1: row rowA+2+rsel, values v[it][2], v[it][3]
            const size_t rowOff = (size_t)(rowA + 2 + rsel) * 4096;
            float2 ra, rb;
            ra.x = o[it][4] + E1.x + v[it][2].x * E1.z;
            ra.y = o[it][5] + E1.y + v[it][2].y * E1.w;
            rb.x = o[it][6] + E1.x + v[it][3].x * E1.z;
            rb.y = o[it][7] + E1.y + v[it][3].y * E1.w;
            *reinterpret_cast<float2*>(out + rowOff + colO)      = ra;
            *reinterpret_cast<float2*>(out + rowOff + colO + 32) = rb;
        }
    }
}

extern "C" void kernel_launch(void* const* d_in, const int* in_sizes, int n_in,
                              void* d_out, int out_size) {
    const float* A      = (const float*)d_in[0];
    const float* w1     = (const float*)d_in[1];
    const float* b1     = (const float*)d_in[2];
    const float* emb_h  = (const float*)d_in[3];
    const float* emb_w  = (const float*)d_in[4];
    const float* w2     = (const float*)d_in[5];
    const float* b2     = (const float*)d_in[6];
    const float* scales = (const float*)d_in[7];
    float* out = (float*)d_out;
    (void)in_sizes; (void)n_in; (void)out_size;

    pack_kernel<<<256, 256>>>(w1, b1, emb_h, emb_w, w2, b2, scales);
    adapter_mma_kernel<<<4096, 256>>>(A, out);
}

// round 15
// speedup vs baseline: 1.0640x; 1.0640x over previous
#include <cuda_runtime.h>
#include <cuda_fp16.h>

// ---------- packed f16x2 helpers ----------
__device__ __forceinline__ unsigned pkhf(float lo, float hi) {
    unsigned d; asm("cvt.rn.f16x2.f32 %0, %1, %2;" : "=r"(d) : "f"(hi), "f"(lo)); return d;
}
__device__ __forceinline__ unsigned hmin2(unsigned a, unsigned b) {
    unsigned d; asm("min.f16x2 %0, %1, %2;" : "=r"(d) : "r"(a), "r"(b)); return d;
}
__device__ __forceinline__ unsigned hmax2(unsigned a, unsigned b) {
    unsigned d; asm("max.f16x2 %0, %1, %2;" : "=r"(d) : "r"(a), "r"(b)); return d;
}
__device__ __forceinline__ unsigned hadd2(unsigned a, unsigned b) {
    unsigned d; asm("add.rn.f16x2 %0, %1, %2;" : "=r"(d) : "r"(a), "r"(b)); return d;
}
__device__ __forceinline__ unsigned hex2(unsigned a) {
    unsigned d; asm("ex2.approx.f16x2 %0, %1;" : "=r"(d) : "r"(a)); return d;
}
__device__ __forceinline__ unsigned hfma2(unsigned a, unsigned b, unsigned c) {
    unsigned d; asm("fma.rn.f16x2 %0, %1, %2, %3;" : "=r"(d) : "r"(a), "r"(b), "r"(c)); return d;
}
// x = h*log2e (f16x2). Returns elu(h)+1 = max(x,0)*ln2 + exp2(min(x,0)).
__device__ __forceinline__ unsigned elu2h(unsigned x, unsigned ln2) {
    return hfma2(hmax2(x, 0u), ln2, hex2(hmin2(x, 0u)));
}
// layer-1 MMA: f16 inputs, f16 accumulators (D packed f16x2, 2 regs)
__device__ __forceinline__ void mma_h(unsigned& d0, unsigned& d1,
                                      unsigned a0, unsigned a1, unsigned a2, unsigned a3,
                                      unsigned b0, unsigned b1) {
    asm("mma.sync.aligned.m16n8k16.row.col.f16.f16.f16.f16 "
        "{%0,%1},{%2,%3,%4,%5},{%6,%7},{%0,%1};"
        : "+r"(d0), "+r"(d1)
        : "r"(a0), "r"(a1), "r"(a2), "r"(a3), "r"(b0), "r"(b1));
}
// layer-2 MMA: f16 inputs, f32 accumulators
__device__ __forceinline__ void mma_f(float& d0, float& d1, float& d2, float& d3,
                                      unsigned a0, unsigned a1, unsigned a2, unsigned a3,
                                      unsigned b0, unsigned b1) {
    asm("mma.sync.aligned.m16n8k16.row.col.f32.f16.f16.f32 "
        "{%0,%1,%2,%3},{%4,%5,%6,%7},{%8,%9},{%0,%1,%2,%3};"
        : "+f"(d0), "+f"(d1), "+f"(d2), "+f"(d3)
        : "r"(a0), "r"(a1), "r"(a2), "r"(a3), "r"(b0), "r"(b1));
}

// ---------- precomputed packed buffers (one entry per weight-block) ----------
__device__ uint4    g_w1c[256][192];   // [q][kb][g]: 4 f16x2 k-pairs of w1*log2e
__device__ uint4    g_w2c[256][192];   // [(4kb+q)][g]: f16x2 h-pairs, n=g / n=g+8
__device__ uint2    g_bbp[256][24];    // [4kb+q]: f16x2 bias pairs (sub0, sub1), *log2e
__device__ float4   g_eps[256][8];     // [j]: {b2e[2j], b2e[2j+1], sc[2j], sc[2j+1]}
__device__ unsigned g_ehp[256][256];   // [t][q]: f16x2 {eh[t][2q],eh[t][2q+1]}*log2e
__device__ unsigned g_ewp[256][256];   // [t][q]: f16x2 {ew[t][2q],ew[t][2q+1]}*log2e

// Pack kernel: stage w1/w2 into smem with fully-coalesced float4 LDGs, then
// pack fragments from smem (cheap LDS) and store coalesced uint4.
__global__ __launch_bounds__(256) void pack_kernel(
    const float* __restrict__ w1, const float* __restrict__ b1,
    const float* __restrict__ emb_h, const float* __restrict__ emb_w,
    const float* __restrict__ w2, const float* __restrict__ b2,
    const float* __restrict__ scales)
{
    __shared__ __align__(16) float sw1[1536];   // [16][96]
    __shared__ __align__(16) float sw2[1536];   // [96][16]
    __shared__ float s_psum[8 * 16];
    const int b   = blockIdx.x;
    const int tid = threadIdx.x;
    const float L2E = 1.44269504f;

    // coalesced stage: 384 float4 each, 256 threads
    {
        const float4* p1 = reinterpret_cast<const float4*>(w1 + b * 1536);
        const float4* p2 = reinterpret_cast<const float4*>(w2 + b * 1536);
        float4* d1 = reinterpret_cast<float4*>(sw1);
        float4* d2 = reinterpret_cast<float4*>(sw2);
        d1[tid] = p1[tid];
        d2[tid] = p2[tid];
        if (tid < 128) {
            d1[256 + tid] = p1[256 + tid];
            d2[256 + tid] = p2[256 + tid];
        }
    }
    __syncthreads();

    // parallel b2_eff colsum partials: 128 threads, 12 f16-rounded adds each
    if (tid < 128) {
        const int o = tid & 15, p = tid >> 4;
        float s = 0.f;
        #pragma unroll
        for (int h = 0; h < 12; ++h)
            s += __half2float(__float2half(sw2[(12 * p + h) * 16 + o]));
        s_psum[p * 16 + o] = s;
    }

    if (tid < 192) {
        // w1 fragment pack (scaled by log2e): idx = q*48 + kb*8 + g
        const int qq = tid / 48, r = tid - qq * 48;
        const int kb = r >> 3, gg = r & 7;
        const int h0 = 16 * kb + gg;
        g_w1c[b][tid] = make_uint4(
            pkhf(L2E * sw1[(2*qq)*96 + h0],       L2E * sw1[(2*qq+1)*96 + h0]),
            pkhf(L2E * sw1[(2*qq+8)*96 + h0],     L2E * sw1[(2*qq+9)*96 + h0]),
            pkhf(L2E * sw1[(2*qq)*96 + h0 + 8],   L2E * sw1[(2*qq+1)*96 + h0 + 8]),
            pkhf(L2E * sw1[(2*qq+8)*96 + h0 + 8], L2E * sw1[(2*qq+9)*96 + h0 + 8]));
        // w2 fragment pack: idx = (4kb+q)*8 + g
        const int kq = tid >> 3, g2 = tid & 7;
        const int hh = (kq >> 2) * 16 + 2 * (kq & 3);
        g_w2c[b][tid] = make_uint4(
            pkhf(sw2[hh*16 + g2],         sw2[(hh+1)*16 + g2]),
            pkhf(sw2[(hh+8)*16 + g2],     sw2[(hh+9)*16 + g2]),
            pkhf(sw2[hh*16 + 8 + g2],     sw2[(hh+1)*16 + 8 + g2]),
            pkhf(sw2[(hh+8)*16 + 8 + g2], sw2[(hh+9)*16 + 8 + g2]));
    }
    if (tid < 24) {   // bias packs (scaled): kq = 4kb+q -> pairs at 16kb+2q, 16kb+8+2q
        const int h0 = (tid >> 2) * 16 + 2 * (tid & 3);
        const float* pb1 = b1 + b * 96;
        g_bbp[b][tid] = make_uint2(
            pkhf(L2E * pb1[h0],     L2E * pb1[h0 + 1]),
            pkhf(L2E * pb1[h0 + 8], L2E * pb1[h0 + 9]));
    }
    {   // positional-emb pairs (scaled): coalesced float2 loads
        const float2 eh = reinterpret_cast<const float2*>(emb_h + b * 512)[tid];
        const float2 ew = reinterpret_cast<const float2*>(emb_w + b * 512)[tid];
        g_ehp[b][tid] = pkhf(L2E * eh.x, L2E * eh.y);
        g_ewp[b][tid] = pkhf(L2E * ew.x, L2E * ew.y);
    }
    __syncthreads();
    if (tid < 16) {   // b2_eff = b2 - colsum(f16(w2)): exact cancellation of +1 shift
        float s = b2[b * 16 + tid];
        #pragma unroll
        for (int p = 0; p < 8; ++p) s -= s_psum[p * 16 + tid];
        float* ef = reinterpret_cast<float*>(g_eps[b]);
        ef[4 * (tid >> 1) + (tid & 1)]     = s;
        ef[4 * (tid >> 1) + 2 + (tid & 1)] = scales[b * 16 + tid];
    }
}

// Fixed shapes: A 4096x4096 fp32; 256 weight-blocks of 64x64=4096 4x4-tiles;
// RNG_HID=96, RNG_POS_EMB=8.
// Grid 4096 CTAs x 256 threads (8 warps); warp w fuses its two M-blocks
// (same tile row, twb0 and twb0+16) kb-by-kb through the hidden dim.
// A-fragment LDGs issue FIRST (before smem staging) so their DRAM latency
// overlaps staging + barrier. A/out use streaming (.cs) hints: each element
// is touched exactly once, keeping packed-weight lines (reused by 16 CTAs
// and across the pack->main boundary) resident in L2.
#define W1Q_STRIDE 50   // uint4 q-stride: bank = (8q+4g)%32, conflict-free
#define W2R_STRIDE 10   // uint4 row-stride: bank = (8q+4g)%32, conflict-free

__device__ __forceinline__ float2 ldcs2(const float* p) {
    float2 r; asm("ld.global.cs.v2.f32 {%0,%1}, [%2];" : "=f"(r.x), "=f"(r.y) : "l"(p)); return r;
}
__device__ __forceinline__ void stcs2(float* p, float2 v) {
    asm("st.global.cs.v2.f32 [%0], {%1,%2};" :: "l"(p), "f"(v.x), "f"(v.y) : "memory");
}

__global__ __launch_bounds__(256, 3) void adapter_mma_kernel(
    const float* __restrict__ A,        // [4096,4096]
    float* __restrict__ out)            // [4096,4096]
{
    __shared__ __align__(16) uint4    s_w1c[4 * W1Q_STRIDE];
    __shared__ __align__(16) uint4    s_w2c[24 * W2R_STRIDE];
    __shared__ __align__(16) uint2    s_bbp[24];
    __shared__ __align__(16) unsigned s_ehp[256];
    __shared__ __align__(16) unsigned s_ewp[256];
    __shared__ __align__(16) float4   s_eps[8];

    const int b     = blockIdx.x >> 4;
    const int chunk = blockIdx.x & 15;
    const int tid   = threadIdx.x;
    const int warp  = tid >> 5;
    const int lane  = tid & 31;
    const int g     = lane >> 2;     // 0..7
    const int q     = lane & 3;      // 0..3

    // ---- geometry (both M-blocks share tile row; twb1 = twb0 + 16) ----
    const int brow = (b >> 4) << 8;
    const int bcol = (b & 15) << 8;
    const int th   = chunk * 4 + (warp >> 1);
    const int twb0 = (warp & 1) << 5;           // 0 or 32
    const int rowA = brow + th * 4;
    const int rsel = q >> 1;

    // ---- A fragments FIRST: DRAM latency overlaps staging below ----
    const float* pr0 = A + (size_t)(rowA + rsel)     * 4096 + bcol + (twb0 + g) * 4 + 2 * (q & 1);
    const float* pr2 = A + (size_t)(rowA + 2 + rsel) * 4096 + bcol + (twb0 + g) * 4 + 2 * (q & 1);
    float2 v[2][4];
    v[0][0] = ldcs2(pr0);
    v[0][1] = ldcs2(pr0 + 32);
    v[0][2] = ldcs2(pr2);
    v[0][3] = ldcs2(pr2 + 32);
    v[1][0] = ldcs2(pr0 + 64);
    v[1][1] = ldcs2(pr0 + 96);
    v[1][2] = ldcs2(pr2 + 64);
    v[1][3] = ldcs2(pr2 + 96);

    // ---- staging: straight vectorized copies of prepacked data ----
    if (tid < 192) {
        const int qq = tid / 48, r = tid - qq * 48;
        s_w1c[qq * W1Q_STRIDE + r] = g_w1c[b][tid];
        const int kq = tid >> 3, gg = tid & 7;
        s_w2c[kq * W2R_STRIDE + gg] = g_w2c[b][tid];
    } else {
        const int j = tid - 192;   // 0..63
        reinterpret_cast<uint4*>(s_ehp)[j] = reinterpret_cast<const uint4*>(g_ehp[b])[j];
        reinterpret_cast<uint4*>(s_ewp)[j] = reinterpret_cast<const uint4*>(g_ewp[b])[j];
    }
    if (tid < 24)            s_bbp[tid] = g_bbp[b][tid];
    else if (tid < 32)       s_eps[tid - 24] = g_eps[b][tid - 24];

    unsigned Af[2][4];
    #pragma unroll
    for (int it = 0; it < 2; ++it)
        #pragma unroll
        for (int j = 0; j < 4; ++j) Af[it][j] = pkhf(v[it][j].x, v[it][j].y);

    __syncthreads();

    const unsigned PK_LN2 = pkhf(0.69314718f, 0.69314718f);

    float o[2][8];
    #pragma unroll
    for (int it = 0; it < 2; ++it)
        #pragma unroll
        for (int j = 0; j < 8; ++j) o[it][j] = 0.f;

    // ---- fused mainloop: 6 kb-steps over hidden dim ----
    #pragma unroll
    for (int kb = 0; kb < 6; ++kb) {
        const uint4 W1 = s_w1c[q * W1Q_STRIDE + kb * 8 + g];
        const uint2 BB = s_bbp[kb * 4 + q];
        unsigned ka[2][4];
        // sub 0 (hidden cols 16kb+2q, +1): C-init = bias (+ row emb at kb==0)
        {
            unsigned c0 = BB.x;
            if (kb == 0) c0 = hadd2(c0, s_ehp[th * 4 + q]);
            #pragma unroll
            for (int it = 0; it < 2; ++it) {
                unsigned d0 = c0, d1 = c0;
                mma_h(d0, d1, Af[it][0], Af[it][1], Af[it][2], Af[it][3], W1.x, W1.y);
                ka[it][0] = elu2h(d0, PK_LN2);
                ka[it][1] = elu2h(d1, PK_LN2);
            }
        }
        // sub 1 (hidden cols 16kb+8+2q, +1): C-init = bias (+ col emb at kb==0)
        {
            #pragma unroll
            for (int it = 0; it < 2; ++it) {
                unsigned d0 = BB.y, d1 = BB.y;
                if (kb == 0) {
                    const int twb = twb0 + 16 * it;
                    d0 = hadd2(d0, s_ewp[(twb + g) * 4 + q]);
                    d1 = hadd2(d1, s_ewp[(twb + g + 8) * 4 + q]);
                }
                mma_h(d0, d1, Af[it][0], Af[it][1], Af[it][2], Af[it][3], W1.z, W1.w);
                ka[it][2] = elu2h(d0, PK_LN2);
                ka[it][3] = elu2h(d1, PK_LN2);
            }
        }
        // layer-2 k-step: both n-blocks from one LDS.128
        const uint4 W2 = s_w2c[(4 * kb + q) * W2R_STRIDE + g];
        #pragma unroll
        for (int it = 0; it < 2; ++it) {
            mma_f(o[it][0], o[it][1], o[it][2], o[it][3],
                  ka[it][0], ka[it][1], ka[it][2], ka[it][3], W2.x, W2.y);
            mma_f(o[it][4], o[it][5], o[it][6], o[it][7],
                  ka[it][0], ka[it][1], ka[it][2], ka[it][3], W2.z, W2.w);
        }
    }

    // ---- epilogue: out = mlp + b2_eff + flat*scales (flat = register v) ----
    const float4 E0 = s_eps[q];       // ob = 2q
    const float4 E1 = s_eps[4 + q];   // ob = 8+2q
    #pragma unroll
    for (int it = 0; it < 2; ++it) {
        const int colO = bcol + (twb0 + 16 * it + g) * 4 + 2 * (q & 1);
        {   // nb2 = 0: row rowA+rsel, values v[it][0], v[it][1]
            const size_t rowOff = (size_t)(rowA + rsel) * 4096;
            float2 ra, rb;
            ra.x = o[it][0] + E0.x + v[it][0].x * E0.z;
            ra.y = o[it][1] + E0.y + v[it][0].y * E0.w;
            rb.x = o[it][2] + E0.x + v[it][1].x * E0.z;
            rb.y = o[it][3] + E0.y + v[it][1].y * E0.w;
            stcs2(out + rowOff + colO,      ra);
            stcs2(out + rowOff + colO + 32, rb);
        }
        {   // nb2 = 1: row rowA+2+rsel, values v[it][2], v[it][3]
            const size_t rowOff = (size_t)(rowA + 2 + rsel) * 4096;
            float2 ra, rb;
            ra.x = o[it][4] + E1.x + v[it][2].x * E1.z;
            ra.y = o[it][5] + E1.y + v[it][2].y * E1.w;
            rb.x = o[it][6] + E1.x + v[it][3].x * E1.z;
            rb.y = o[it][7] + E1.y + v[it][3].y * E1.w;
            stcs2(out + rowOff + colO,      ra);
            stcs2(out + rowOff + colO + 32, rb);
        }
    }
}

extern "C" void kernel_launch(void* const* d_in, const int* in_sizes, int n_in,
                              void* d_out, int out_size) {
    const float* A      = (const float*)d_in[0];
    const float* w1     = (const float*)d_in[1];
    const float* b1     = (const float*)d_in[2];
    const float* emb_h  = (const float*)d_in[3];
    const float* emb_w  = (const float*)d_in[4];
    const float* w2     = (const float*)d_in[5];
    const float* b2     = (const float*)d_in[6];
    const float* scales = (const float*)d_in[7];
    float* out = (float*)d_out;
    (void)in_sizes; (void)n_in; (void)out_size;

    pack_kernel<<<256, 256>>>(w1, b1, emb_h, emb_w, w2, b2, scales);
    adapter_mma_kernel<<<4096, 256>>>(A, out);
}

// round 16
// speedup vs baseline: 1.1150x; 1.0480x over previous
#include <cuda_runtime.h>
#include <cuda_fp16.h>

// ---------- packed f16x2 helpers ----------
__device__ __forceinline__ unsigned pkhf(float lo, float hi) {
    unsigned d; asm("cvt.rn.f16x2.f32 %0, %1, %2;" : "=r"(d) : "f"(hi), "f"(lo)); return d;
}
__device__ __forceinline__ unsigned hmin2(unsigned a, unsigned b) {
    unsigned d; asm("min.f16x2 %0, %1, %2;" : "=r"(d) : "r"(a), "r"(b)); return d;
}
__device__ __forceinline__ unsigned hmax2(unsigned a, unsigned b) {
    unsigned d; asm("max.f16x2 %0, %1, %2;" : "=r"(d) : "r"(a), "r"(b)); return d;
}
__device__ __forceinline__ unsigned hadd2(unsigned a, unsigned b) {
    unsigned d; asm("add.rn.f16x2 %0, %1, %2;" : "=r"(d) : "r"(a), "r"(b)); return d;
}
__device__ __forceinline__ unsigned hex2(unsigned a) {
    unsigned d; asm("ex2.approx.f16x2 %0, %1;" : "=r"(d) : "r"(a)); return d;
}
__device__ __forceinline__ unsigned hfma2(unsigned a, unsigned b, unsigned c) {
    unsigned d; asm("fma.rn.f16x2 %0, %1, %2, %3;" : "=r"(d) : "r"(a), "r"(b), "r"(c)); return d;
}
// x = h*log2e (f16x2). Returns elu(h)+1 = max(x,0)*ln2 + exp2(min(x,0)).
__device__ __forceinline__ unsigned elu2h(unsigned x, unsigned ln2) {
    return hfma2(hmax2(x, 0u), ln2, hex2(hmin2(x, 0u)));
}
// layer-1 MMA: f16 inputs, f16 accumulators (D packed f16x2, 2 regs)
__device__ __forceinline__ void mma_h(unsigned& d0, unsigned& d1,
                                      unsigned a0, unsigned a1, unsigned a2, unsigned a3,
                                      unsigned b0, unsigned b1) {
    asm("mma.sync.aligned.m16n8k16.row.col.f16.f16.f16.f16 "
        "{%0,%1},{%2,%3,%4,%5},{%6,%7},{%0,%1};"
        : "+r"(d0), "+r"(d1)
        : "r"(a0), "r"(a1), "r"(a2), "r"(a3), "r"(b0), "r"(b1));
}
// layer-2 MMA: f16 inputs, f32 accumulators
__device__ __forceinline__ void mma_f(float& d0, float& d1, float& d2, float& d3,
                                      unsigned a0, unsigned a1, unsigned a2, unsigned a3,
                                      unsigned b0, unsigned b1) {
    asm("mma.sync.aligned.m16n8k16.row.col.f32.f16.f16.f32 "
        "{%0,%1,%2,%3},{%4,%5,%6,%7},{%8,%9},{%0,%1,%2,%3};"
        : "+f"(d0), "+f"(d1), "+f"(d2), "+f"(d3)
        : "r"(a0), "r"(a1), "r"(a2), "r"(a3), "r"(b0), "r"(b1));
}

// ---------- precomputed packed buffers (one entry per weight-block) ----------
__device__ uint4    g_w1c[256][192];   // [q][kb][g]: 4 f16x2 k-pairs of w1*log2e
__device__ uint4    g_w2c[256][192];   // [(4kb+q)][g]: f16x2 h-pairs, n=g / n=g+8
__device__ uint2    g_bbp[256][24];    // [4kb+q]: f16x2 bias pairs (sub0, sub1), *log2e
__device__ float4   g_eps[256][8];     // [j]: {b2e[2j], b2e[2j+1], sc[2j], sc[2j+1]}
__device__ unsigned g_ehp[256][256];   // [t][q]: f16x2 {eh[t][2q],eh[t][2q+1]}*log2e
__device__ unsigned g_ewp[256][256];   // [t][q]: f16x2 {ew[t][2q],ew[t][2q+1]}*log2e

// Pack kernel: stage w1/w2 into smem with fully-coalesced float4 LDGs, then
// pack fragments from smem (cheap LDS) and store coalesced uint4.
__global__ __launch_bounds__(256) void pack_kernel(
    const float* __restrict__ w1, const float* __restrict__ b1,
    const float* __restrict__ emb_h, const float* __restrict__ emb_w,
    const float* __restrict__ w2, const float* __restrict__ b2,
    const float* __restrict__ scales)
{
    __shared__ __align__(16) float sw1[1536];   // [16][96]
    __shared__ __align__(16) float sw2[1536];   // [96][16]
    __shared__ float s_psum[8 * 16];
    const int b   = blockIdx.x;
    const int tid = threadIdx.x;
    const float L2E = 1.44269504f;

    // coalesced stage: 384 float4 each, 256 threads
    {
        const float4* p1 = reinterpret_cast<const float4*>(w1 + b * 1536);
        const float4* p2 = reinterpret_cast<const float4*>(w2 + b * 1536);
        float4* d1 = reinterpret_cast<float4*>(sw1);
        float4* d2 = reinterpret_cast<float4*>(sw2);
        d1[tid] = p1[tid];
        d2[tid] = p2[tid];
        if (tid < 128) {
            d1[256 + tid] = p1[256 + tid];
            d2[256 + tid] = p2[256 + tid];
        }
    }
    __syncthreads();

    // parallel b2_eff colsum partials: 128 threads, 12 f16-rounded adds each
    if (tid < 128) {
        const int o = tid & 15, p = tid >> 4;
        float s = 0.f;
        #pragma unroll
        for (int h = 0; h < 12; ++h)
            s += __half2float(__float2half(sw2[(12 * p + h) * 16 + o]));
        s_psum[p * 16 + o] = s;
    }

    if (tid < 192) {
        // w1 fragment pack (scaled by log2e): idx = q*48 + kb*8 + g
        const int qq = tid / 48, r = tid - qq * 48;
        const int kb = r >> 3, gg = r & 7;
        const int h0 = 16 * kb + gg;
        g_w1c[b][tid] = make_uint4(
            pkhf(L2E * sw1[(2*qq)*96 + h0],       L2E * sw1[(2*qq+1)*96 + h0]),
            pkhf(L2E * sw1[(2*qq+8)*96 + h0],     L2E * sw1[(2*qq+9)*96 + h0]),
            pkhf(L2E * sw1[(2*qq)*96 + h0 + 8],   L2E * sw1[(2*qq+1)*96 + h0 + 8]),
            pkhf(L2E * sw1[(2*qq+8)*96 + h0 + 8], L2E * sw1[(2*qq+9)*96 + h0 + 8]));
        // w2 fragment pack: idx = (4kb+q)*8 + g
        const int kq = tid >> 3, g2 = tid & 7;
        const int hh = (kq >> 2) * 16 + 2 * (kq & 3);
        g_w2c[b][tid] = make_uint4(
            pkhf(sw2[hh*16 + g2],         sw2[(hh+1)*16 + g2]),
            pkhf(sw2[(hh+8)*16 + g2],     sw2[(hh+9)*16 + g2]),
            pkhf(sw2[hh*16 + 8 + g2],     sw2[(hh+1)*16 + 8 + g2]),
            pkhf(sw2[(hh+8)*16 + 8 + g2], sw2[(hh+9)*16 + 8 + g2]));
    }
    if (tid < 24) {   // bias packs (scaled): kq = 4kb+q -> pairs at 16kb+2q, 16kb+8+2q
        const int h0 = (tid >> 2) * 16 + 2 * (tid & 3);
        const float* pb1 = b1 + b * 96;
        g_bbp[b][tid] = make_uint2(
            pkhf(L2E * pb1[h0],     L2E * pb1[h0 + 1]),
            pkhf(L2E * pb1[h0 + 8], L2E * pb1[h0 + 9]));
    }
    {   // positional-emb pairs (scaled): coalesced float2 loads
        const float2 eh = reinterpret_cast<const float2*>(emb_h + b * 512)[tid];
        const float2 ew = reinterpret_cast<const float2*>(emb_w + b * 512)[tid];
        g_ehp[b][tid] = pkhf(L2E * eh.x, L2E * eh.y);
        g_ewp[b][tid] = pkhf(L2E * ew.x, L2E * ew.y);
    }
    __syncthreads();
    if (tid < 16) {   // b2_eff = b2 - colsum(f16(w2)): exact cancellation of +1 shift
        float s = b2[b * 16 + tid];
        #pragma unroll
        for (int p = 0; p < 8; ++p) s -= s_psum[p * 16 + tid];
        float* ef = reinterpret_cast<float*>(g_eps[b]);
        ef[4 * (tid >> 1) + (tid & 1)]     = s;
        ef[4 * (tid >> 1) + 2 + (tid & 1)] = scales[b * 16 + tid];
    }
}

// Fixed shapes: A 4096x4096 fp32; 256 weight-blocks of 64x64=4096 4x4-tiles;
// RNG_HID=96, RNG_POS_EMB=8.
// Grid 2048 CTAs x 256 threads (8 warps). Warp w owns ONE FULL TILE ROW
// (tr = rpair*8 + w): 64 tiles = 4 M-blocks at twb = 0/16/32/48, all fused in
// one kb-mainloop so every weight-fragment LDS serves 4 M-blocks. All 16
// A-fragment LDGs are front-batched (no serial phases). A/out use .cs hints.
#define W1Q_STRIDE 50   // uint4 q-stride: bank = (8q+4g)%32, conflict-free
#define W2R_STRIDE 10   // uint4 row-stride: bank = (8q+4g)%32, conflict-free

__device__ __forceinline__ float2 ldcs2(const float* p) {
    float2 r; asm("ld.global.cs.v2.f32 {%0,%1}, [%2];" : "=f"(r.x), "=f"(r.y) : "l"(p)); return r;
}
__device__ __forceinline__ void stcs2(float* p, float2 v) {
    asm("st.global.cs.v2.f32 [%0], {%1,%2};" :: "l"(p), "f"(v.x), "f"(v.y) : "memory");
}

__global__ __launch_bounds__(256, 2) void adapter_mma_kernel(
    const float* __restrict__ A,        // [4096,4096]
    float* __restrict__ out)            // [4096,4096]
{
    __shared__ __align__(16) uint4    s_w1c[4 * W1Q_STRIDE];
    __shared__ __align__(16) uint4    s_w2c[24 * W2R_STRIDE];
    __shared__ __align__(16) uint2    s_bbp[24];
    __shared__ __align__(16) unsigned s_ehp[256];
    __shared__ __align__(16) unsigned s_ewp[256];
    __shared__ __align__(16) float4   s_eps[8];

    const int b     = blockIdx.x >> 3;   // weight-block 0..255
    const int rpair = blockIdx.x & 7;    // group of 8 tile rows
    const int tid   = threadIdx.x;
    const int warp  = tid >> 5;
    const int lane  = tid & 31;
    const int g     = lane >> 2;     // 0..7
    const int q     = lane & 3;      // 0..3

    // ---- geometry: warp owns tile row th; its 4 M-blocks at twb = 16*it ----
    const int brow = (b >> 4) << 8;
    const int bcol = (b & 15) << 8;
    const int th   = rpair * 8 + warp;          // 0..63
    const int rowA = brow + th * 4;
    const int rsel = q >> 1;

    // ---- A fragments FIRST: DRAM latency overlaps staging below ----
    const float* pr0 = A + (size_t)(rowA + rsel)     * 4096 + bcol + g * 4 + 2 * (q & 1);
    const float* pr2 = A + (size_t)(rowA + 2 + rsel) * 4096 + bcol + g * 4 + 2 * (q & 1);
    float2 v[4][4];
    #pragma unroll
    for (int it = 0; it < 4; ++it) {
        const int base = it * 64;
        v[it][0] = ldcs2(pr0 + base);
        v[it][1] = ldcs2(pr0 + base + 32);
        v[it][2] = ldcs2(pr2 + base);
        v[it][3] = ldcs2(pr2 + base + 32);
    }

    // ---- staging: straight vectorized copies of prepacked data ----
    if (tid < 192) {
        const int qq = tid / 48, r = tid - qq * 48;
        s_w1c[qq * W1Q_STRIDE + r] = g_w1c[b][tid];
        const int kq = tid >> 3, gg = tid & 7;
        s_w2c[kq * W2R_STRIDE + gg] = g_w2c[b][tid];
    } else {
        const int j = tid - 192;   // 0..63
        reinterpret_cast<uint4*>(s_ehp)[j] = reinterpret_cast<const uint4*>(g_ehp[b])[j];
        reinterpret_cast<uint4*>(s_ewp)[j] = reinterpret_cast<const uint4*>(g_ewp[b])[j];
    }
    if (tid < 24)            s_bbp[tid] = g_bbp[b][tid];
    else if (tid < 32)       s_eps[tid - 24] = g_eps[b][tid - 24];

    unsigned Af[4][4];
    #pragma unroll
    for (int it = 0; it < 4; ++it)
        #pragma unroll
        for (int j = 0; j < 4; ++j) Af[it][j] = pkhf(v[it][j].x, v[it][j].y);

    __syncthreads();

    const unsigned PK_LN2 = pkhf(0.69314718f, 0.69314718f);

    float o[4][8];
    #pragma unroll
    for (int it = 0; it < 4; ++it)
        #pragma unroll
        for (int j = 0; j < 8; ++j) o[it][j] = 0.f;

    // ---- fused mainloop: 6 kb-steps over hidden dim, 4 M-blocks per step ----
    #pragma unroll
    for (int kb = 0; kb < 6; ++kb) {
        const uint4 W1 = s_w1c[q * W1Q_STRIDE + kb * 8 + g];
        const uint2 BB = s_bbp[kb * 4 + q];
        unsigned ka[4][4];
        // sub 0 (hidden cols 16kb+2q, +1): C-init = bias (+ row emb at kb==0,
        // shared by all 4 M-blocks of this tile row)
        {
            unsigned c0 = BB.x;
            if (kb == 0) c0 = hadd2(c0, s_ehp[th * 4 + q]);
            #pragma unroll
            for (int it = 0; it < 4; ++it) {
                unsigned d0 = c0, d1 = c0;
                mma_h(d0, d1, Af[it][0], Af[it][1], Af[it][2], Af[it][3], W1.x, W1.y);
                ka[it][0] = elu2h(d0, PK_LN2);
                ka[it][1] = elu2h(d1, PK_LN2);
            }
        }
        // sub 1 (hidden cols 16kb+8+2q, +1): C-init = bias (+ col emb at kb==0)
        {
            #pragma unroll
            for (int it = 0; it < 4; ++it) {
                unsigned d0 = BB.y, d1 = BB.y;
                if (kb == 0) {
                    const int twb = 16 * it;
                    d0 = hadd2(d0, s_ewp[(twb + g) * 4 + q]);
                    d1 = hadd2(d1, s_ewp[(twb + g + 8) * 4 + q]);
                }
                mma_h(d0, d1, Af[it][0], Af[it][1], Af[it][2], Af[it][3], W1.z, W1.w);
                ka[it][2] = elu2h(d0, PK_LN2);
                ka[it][3] = elu2h(d1, PK_LN2);
            }
        }
        // layer-2 k-step: both n-blocks from one LDS.128, shared by 4 M-blocks
        const uint4 W2 = s_w2c[(4 * kb + q) * W2R_STRIDE + g];
        #pragma unroll
        for (int it = 0; it < 4; ++it) {
            mma_f(o[it][0], o[it][1], o[it][2], o[it][3],
                  ka[it][0], ka[it][1], ka[it][2], ka[it][3], W2.x, W2.y);
            mma_f(o[it][4], o[it][5], o[it][6], o[it][7],
                  ka[it][0], ka[it][1], ka[it][2], ka[it][3], W2.z, W2.w);
        }
    }

    // ---- epilogue: out = mlp + b2_eff + flat*scales (flat = register v) ----
    const float4 E0 = s_eps[q];       // ob = 2q
    const float4 E1 = s_eps[4 + q];   // ob = 8+2q
    #pragma unroll
    for (int it = 0; it < 4; ++it) {
        const int colO = bcol + (16 * it + g) * 4 + 2 * (q & 1);
        {   // nb2 = 0: row rowA+rsel, values v[it][0], v[it][1]
            const size_t rowOff = (size_t)(rowA + rsel) * 4096;
            float2 ra, rb;
            ra.x = o[it][0] + E0.x + v[it][0].x * E0.z;
            ra.y = o[it][1] + E0.y + v[it][0].y * E0.w;
            rb.x = o[it][2] + E0.x + v[it][1].x * E0.z;
            rb.y = o[it][3] + E0.y + v[it][1].y * E0.w;
            stcs2(out + rowOff + colO,      ra);
            stcs2(out + rowOff + colO + 32, rb);
        }
        {   // nb2 = 1: row rowA+2+rsel, values v[it][2], v[it][3]
            const size_t rowOff = (size_t)(rowA + 2 + rsel) * 4096;
            float2 ra, rb;
            ra.x = o[it][4] + E1.x + v[it][2].x * E1.z;
            ra.y = o[it][5] + E1.y + v[it][2].y * E1.w;
            rb.x = o[it][6] + E1.x + v[it][3].x * E1.z;
            rb.y = o[it][7] + E1.y + v[it][3].y * E1.w;
            stcs2(out + rowOff + colO,      ra);
            stcs2(out + rowOff + colO + 32, rb);
        }
    }
}

extern "C" void kernel_launch(void* const* d_in, const int* in_sizes, int n_in,
                              void* d_out, int out_size) {
    const float* A      = (const float*)d_in[0];
    const float* w1     = (const float*)d_in[1];
    const float* b1     = (const float*)d_in[2];
    const float* emb_h  = (const float*)d_in[3];
    const float* emb_w  = (const float*)d_in[4];
    const float* w2     = (const float*)d_in[5];
    const float* b2     = (const float*)d_in[6];
    const float* scales = (const float*)d_in[7];
    float* out = (float*)d_out;
    (void)in_sizes; (void)n_in; (void)out_size;

    pack_kernel<<<256, 256>>>(w1, b1, emb_h, emb_w, w2, b2, scales);
    adapter_mma_kernel<<<2048, 256>>>(A, out);
}

// round 17
// speedup vs baseline: 1.1294x; 1.0128x over previous
#include <cuda_runtime.h>
#include <cuda_fp16.h>

// ---------- packed f16x2 helpers ----------
__device__ __forceinline__ unsigned pkhf(float lo, float hi) {
    unsigned d; asm("cvt.rn.f16x2.f32 %0, %1, %2;" : "=r"(d) : "f"(hi), "f"(lo)); return d;
}
__device__ __forceinline__ unsigned hmin2(unsigned a, unsigned b) {
    unsigned d; asm("min.f16x2 %0, %1, %2;" : "=r"(d) : "r"(a), "r"(b)); return d;
}
__device__ __forceinline__ unsigned hmax2(unsigned a, unsigned b) {
    unsigned d; asm("max.f16x2 %0, %1, %2;" : "=r"(d) : "r"(a), "r"(b)); return d;
}
__device__ __forceinline__ unsigned hadd2(unsigned a, unsigned b) {
    unsigned d; asm("add.rn.f16x2 %0, %1, %2;" : "=r"(d) : "r"(a), "r"(b)); return d;
}
__device__ __forceinline__ unsigned hex2(unsigned a) {
    unsigned d; asm("ex2.approx.f16x2 %0, %1;" : "=r"(d) : "r"(a)); return d;
}
__device__ __forceinline__ unsigned hfma2(unsigned a, unsigned b, unsigned c) {
    unsigned d; asm("fma.rn.f16x2 %0, %1, %2, %3;" : "=r"(d) : "r"(a), "r"(b), "r"(c)); return d;
}
// x = h*log2e (f16x2). Returns elu(h)+1 = max(x,0)*ln2 + exp2(min(x,0)).
__device__ __forceinline__ unsigned elu2h(unsigned x, unsigned ln2) {
    return hfma2(hmax2(x, 0u), ln2, hex2(hmin2(x, 0u)));
}
// layer-1 MMA: f16 inputs, f16 accumulators (D packed f16x2, 2 regs)
__device__ __forceinline__ void mma_h(unsigned& d0, unsigned& d1,
                                      unsigned a0, unsigned a1, unsigned a2, unsigned a3,
                                      unsigned b0, unsigned b1) {
    asm("mma.sync.aligned.m16n8k16.row.col.f16.f16.f16.f16 "
        "{%0,%1},{%2,%3,%4,%5},{%6,%7},{%0,%1};"
        : "+r"(d0), "+r"(d1)
        : "r"(a0), "r"(a1), "r"(a2), "r"(a3), "r"(b0), "r"(b1));
}
// layer-2 MMA: f16 inputs, f32 accumulators
__device__ __forceinline__ void mma_f(float& d0, float& d1, float& d2, float& d3,
                                      unsigned a0, unsigned a1, unsigned a2, unsigned a3,
                                      unsigned b0, unsigned b1) {
    asm("mma.sync.aligned.m16n8k16.row.col.f32.f16.f16.f32 "
        "{%0,%1,%2,%3},{%4,%5,%6,%7},{%8,%9},{%0,%1,%2,%3};"
        : "+f"(d0), "+f"(d1), "+f"(d2), "+f"(d3)
        : "r"(a0), "r"(a1), "r"(a2), "r"(a3), "r"(b0), "r"(b1));
}

__device__ __forceinline__ float2 ldcs2(const float* p) {
    float2 r; asm("ld.global.cs.v2.f32 {%0,%1}, [%2];" : "=f"(r.x), "=f"(r.y) : "l"(p)); return r;
}
__device__ __forceinline__ void stcs2(float* p, float2 v) {
    asm("st.global.cs.v2.f32 [%0], {%1,%2};" :: "l"(p), "f"(v.x), "f"(v.y) : "memory");
}

// Fixed shapes: A 4096x4096 fp32; 256 weight-blocks of 64x64=4096 4x4-tiles;
// RNG_HID=96, RNG_POS_EMB=8.
// SINGLE fused kernel, grid 2048 CTAs x 256 threads (8 warps). Each CTA:
//   1. issues its 16 A-fragment LDGs (front-batched, .cs)
//   2. stages raw w1/w2 with coalesced float4 LDGs into smem (under the
//      shadow of the A-load DRAM latency), packs fragments smem->smem
//   3. runs the fused MLP mainloop: warp w owns ONE FULL TILE ROW
//      (tr = rpair*8 + w): 64 tiles = 4 M-blocks at twb = 0/16/32/48,
//      sharing every weight-fragment LDS across 4 M-blocks.
#define W1Q_STRIDE 50   // uint4 q-stride: bank = (8q+4g)%32, conflict-free
#define W2R_STRIDE 10   // uint4 row-stride: bank = (8q+4g)%32, conflict-free

__global__ __launch_bounds__(256, 2) void adapter_mma_kernel(
    const float* __restrict__ A,        // [4096,4096]
    const float* __restrict__ w1,       // [256,16,96]
    const float* __restrict__ b1,       // [256,96]
    const float* __restrict__ emb_h,    // [256,64,8]
    const float* __restrict__ emb_w,    // [256,64,8]
    const float* __restrict__ w2,       // [256,96,16]
    const float* __restrict__ b2,       // [256,16]
    const float* __restrict__ scales,   // [256,16]
    float* __restrict__ out)            // [4096,4096]
{
    __shared__ __align__(16) float    sw1[1536];            // raw w1 [16][96]
    __shared__ __align__(16) float    sw2[1536];            // raw w2 [96][16]
    __shared__ __align__(16) uint4    s_w1c[4 * W1Q_STRIDE];
    __shared__ __align__(16) uint4    s_w2c[24 * W2R_STRIDE];
    __shared__ __align__(16) uint2    s_bbp[24];
    __shared__ __align__(16) unsigned s_ehp[256];
    __shared__ __align__(16) unsigned s_ewp[256];
    __shared__ __align__(16) float4   s_eps[8];
    __shared__            float       s_psum[8 * 16];

    const int b     = blockIdx.x >> 3;   // weight-block 0..255
    const int rpair = blockIdx.x & 7;    // group of 8 tile rows
    const int tid   = threadIdx.x;
    const int warp  = tid >> 5;
    const int lane  = tid & 31;
    const int g     = lane >> 2;     // 0..7
    const int q     = lane & 3;      // 0..3
    const float L2E = 1.44269504f;

    // ---- geometry: warp owns tile row th; its 4 M-blocks at twb = 16*it ----
    const int brow = (b >> 4) << 8;
    const int bcol = (b & 15) << 8;
    const int th   = rpair * 8 + warp;          // 0..63
    const int rowA = brow + th * 4;
    const int rsel = q >> 1;

    // ---- phase 0: A fragments FIRST (DRAM latency covers all packing) ----
    const float* pr0 = A + (size_t)(rowA + rsel)     * 4096 + bcol + g * 4 + 2 * (q & 1);
    const float* pr2 = A + (size_t)(rowA + 2 + rsel) * 4096 + bcol + g * 4 + 2 * (q & 1);
    float2 v[4][4];
    #pragma unroll
    for (int it = 0; it < 4; ++it) {
        const int base = it * 64;
        v[it][0] = ldcs2(pr0 + base);
        v[it][1] = ldcs2(pr0 + base + 32);
        v[it][2] = ldcs2(pr2 + base);
        v[it][3] = ldcs2(pr2 + base + 32);
    }

    // ---- phase 1: coalesced raw-weight stage + emb pack ----
    {
        const float4* p1 = reinterpret_cast<const float4*>(w1 + b * 1536);
        const float4* p2 = reinterpret_cast<const float4*>(w2 + b * 1536);
        float4* d1 = reinterpret_cast<float4*>(sw1);
        float4* d2 = reinterpret_cast<float4*>(sw2);
        d1[tid] = p1[tid];
        d2[tid] = p2[tid];
        if (tid < 128) {
            d1[256 + tid] = p1[256 + tid];
            d2[256 + tid] = p2[256 + tid];
        }
        const float2 eh = reinterpret_cast<const float2*>(emb_h + b * 512)[tid];
        const float2 ew = reinterpret_cast<const float2*>(emb_w + b * 512)[tid];
        s_ehp[tid] = pkhf(L2E * eh.x, L2E * eh.y);
        s_ewp[tid] = pkhf(L2E * ew.x, L2E * ew.y);
    }
    __syncthreads();

    // ---- phase 2: pack fragments smem->smem ----
    if (tid < 128) {   // b2_eff colsum partials: 12 f16-rounded adds each
        const int o = tid & 15, p = tid >> 4;
        float s = 0.f;
        #pragma unroll
        for (int h = 0; h < 12; ++h)
            s += __half2float(__float2half(sw2[(12 * p + h) * 16 + o]));
        s_psum[p * 16 + o] = s;
    }
    if (tid < 192) {
        // w1 fragment pack (scaled by log2e): idx = q*48 + kb*8 + g
        const int qq = tid / 48, r = tid - qq * 48;
        s_w1c[qq * W1Q_STRIDE + r] = make_uint4(
            pkhf(L2E * sw1[(2*qq)*96   + ((r>>3)*16 + (r&7))],
                 L2E * sw1[(2*qq+1)*96 + ((r>>3)*16 + (r&7))]),
            pkhf(L2E * sw1[(2*qq+8)*96 + ((r>>3)*16 + (r&7))],
                 L2E * sw1[(2*qq+9)*96 + ((r>>3)*16 + (r&7))]),
            pkhf(L2E * sw1[(2*qq)*96   + ((r>>3)*16 + (r&7)) + 8],
                 L2E * sw1[(2*qq+1)*96 + ((r>>3)*16 + (r&7)) + 8]),
            pkhf(L2E * sw1[(2*qq+8)*96 + ((r>>3)*16 + (r&7)) + 8],
                 L2E * sw1[(2*qq+9)*96 + ((r>>3)*16 + (r&7)) + 8]));
        // w2 fragment pack: idx kq = tid>>3 (0..23), g2 = tid&7
        const int kq = tid >> 3, g2 = tid & 7;
        const int hh = (kq >> 2) * 16 + 2 * (kq & 3);
        s_w2c[kq * W2R_STRIDE + g2] = make_uint4(
            pkhf(sw2[hh*16 + g2],         sw2[(hh+1)*16 + g2]),
            pkhf(sw2[(hh+8)*16 + g2],     sw2[(hh+9)*16 + g2]),
            pkhf(sw2[hh*16 + 8 + g2],     sw2[(hh+1)*16 + 8 + g2]),
            pkhf(sw2[(hh+8)*16 + 8 + g2], sw2[(hh+9)*16 + 8 + g2]));
    }
    if (tid >= 192 && tid < 216) {   // bias packs (scaled), kq = tid-192
        const int kq = tid - 192;
        const int h0 = (kq >> 2) * 16 + 2 * (kq & 3);
        const float* pb1 = b1 + b * 96;
        s_bbp[kq] = make_uint2(
            pkhf(L2E * pb1[h0],     L2E * pb1[h0 + 1]),
            pkhf(L2E * pb1[h0 + 8], L2E * pb1[h0 + 9]));
    }
    __syncthreads();
    if (tid < 16) {   // b2_eff = b2 - colsum(f16(w2)): exact +1-shift cancel
        float s = b2[b * 16 + tid];
        #pragma unroll
        for (int p = 0; p < 8; ++p) s -= s_psum[p * 16 + tid];
        float* ef = reinterpret_cast<float*>(s_eps);
        ef[4 * (tid >> 1) + (tid & 1)]     = s;
        ef[4 * (tid >> 1) + 2 + (tid & 1)] = scales[b * 16 + tid];
    }

    unsigned Af[4][4];
    #pragma unroll
    for (int it = 0; it < 4; ++it)
        #pragma unroll
        for (int j = 0; j < 4; ++j) Af[it][j] = pkhf(v[it][j].x, v[it][j].y);

    __syncthreads();

    const unsigned PK_LN2 = pkhf(0.69314718f, 0.69314718f);

    float o[4][8];
    #pragma unroll
    for (int it = 0; it < 4; ++it)
        #pragma unroll
        for (int j = 0; j < 8; ++j) o[it][j] = 0.f;

    // ---- fused mainloop: 6 kb-steps over hidden dim, 4 M-blocks per step ----
    #pragma unroll
    for (int kb = 0; kb < 6; ++kb) {
        const uint4 W1 = s_w1c[q * W1Q_STRIDE + kb * 8 + g];
        const uint2 BB = s_bbp[kb * 4 + q];
        unsigned ka[4][4];
        // sub 0 (hidden cols 16kb+2q, +1): C-init = bias (+ row emb at kb==0,
        // shared by all 4 M-blocks of this tile row)
        {
            unsigned c0 = BB.x;
            if (kb == 0) c0 = hadd2(c0, s_ehp[th * 4 + q]);
            #pragma unroll
            for (int it = 0; it < 4; ++it) {
                unsigned d0 = c0, d1 = c0;
                mma_h(d0, d1, Af[it][0], Af[it][1], Af[it][2], Af[it][3], W1.x, W1.y);
                ka[it][0] = elu2h(d0, PK_LN2);
                ka[it][1] = elu2h(d1, PK_LN2);
            }
        }
        // sub 1 (hidden cols 16kb+8+2q, +1): C-init = bias (+ col emb at kb==0)
        {
            #pragma unroll
            for (int it = 0; it < 4; ++it) {
                unsigned d0 = BB.y, d1 = BB.y;
                if (kb == 0) {
                    const int twb = 16 * it;
                    d0 = hadd2(d0, s_ewp[(twb + g) * 4 + q]);
                    d1 = hadd2(d1, s_ewp[(twb + g + 8) * 4 + q]);
                }
                mma_h(d0, d1, Af[it][0], Af[it][1], Af[it][2], Af[it][3], W1.z, W1.w);
                ka[it][2] = elu2h(d0, PK_LN2);
                ka[it][3] = elu2h(d1, PK_LN2);
            }
        }
        // layer-2 k-step: both n-blocks from one LDS.128, shared by 4 M-blocks
        const uint4 W2 = s_w2c[(4 * kb + q) * W2R_STRIDE + g];
        #pragma unroll
        for (int it = 0; it < 4; ++it) {
            mma_f(o[it][0], o[it][1], o[it][2], o[it][3],
                  ka[it][0], ka[it][1], ka[it][2], ka[it][3], W2.x, W2.y);
            mma_f(o[it][4], o[it][5], o[it][6], o[it][7],
                  ka[it][0], ka[it][1], ka[it][2], ka[it][3], W2.z, W2.w);
        }
    }

    // ---- epilogue: out = mlp + b2_eff + flat*scales (flat = register v) ----
    const float4 E0 = s_eps[q];       // ob = 2q
    const float4 E1 = s_eps[4 + q];   // ob = 8+2q
    #pragma unroll
    for (int it = 0; it < 4; ++it) {
        const int colO = bcol + (16 * it + g) * 4 + 2 * (q & 1);
        {   // nb2 = 0: row rowA+rsel, values v[it][0], v[it][1]
            const size_t rowOff = (size_t)(rowA + rsel) * 4096;
            float2 ra, rb;
            ra.x = o[it][0] + E0.x + v[it][0].x * E0.z;
            ra.y = o[it][1] + E0.y + v[it][0].y * E0.w;
            rb.x = o[it][2] + E0.x + v[it][1].x * E0.z;
            rb.y = o[it][3] + E0.y + v[it][1].y * E0.w;
            stcs2(out + rowOff + colO,      ra);
            stcs2(out + rowOff + colO + 32, rb);
        }
        {   // nb2 = 1: row rowA+2+rsel, values v[it][2], v[it][3]
            const size_t rowOff = (size_t)(rowA + 2 + rsel) * 4096;
            float2 ra, rb;
            ra.x = o[it][4] + E1.x + v[it][2].x * E1.z;
            ra.y = o[it][5] + E1.y + v[it][2].y * E1.w;
            rb.x = o[it][6] + E1.x + v[it][3].x * E1.z;
            rb.y = o[it][7] + E1.y + v[it][3].y * E1.w;
            stcs2(out + rowOff + colO,      ra);
            stcs2(out + rowOff + colO + 32, rb);
        }
    }
}

extern "C" void kernel_launch(void* const* d_in, const int* in_sizes, int n_in,
                              void* d_out, int out_size) {
    const float* A      = (const float*)d_in[0];
    const float* w1     = (const float*)d_in[1];
    const float* b1     = (const float*)d_in[2];
    const float* emb_h  = (const float*)d_in[3];
    const float* emb_w  = (const float*)d_in[4];
    const float* w2     = (const float*)d_in[5];
    const float* b2     = (const float*)d_in[6];
    const float* scales = (const float*)d_in[7];
    float* out = (float*)d_out;
    (void)in_sizes; (void)n_in; (void)out_size;

    adapter_mma_kernel<<<2048, 256>>>(A, w1, b1, emb_h, emb_w, w2, b2, scales, out);
}